// round 8
// baseline (speedup 1.0000x reference)
#include <cuda_runtime.h>
#include <cuda_bf16.h>
#include <math.h>
#include <math_constants.h>
#include <cstdint>

#define BB 4
#define SS 2048
#define DM 1024
#define HH 16
#define DKK 64
#define MTOT (BB*SS)   // 8192

// ---------------- scratch (allocation-free) ----------------
__device__ int8_t g_x1[(size_t)MTOT*DM],  g_x2[(size_t)MTOT*DM];
__device__ int8_t g_w1[(size_t)4*DM*DM],  g_w2[(size_t)4*DM*DM];
__device__ int8_t g_a1[(size_t)MTOT*DM],  g_a2[(size_t)MTOT*DM];
__device__ float  g_sax[MTOT], g_saao[MTOT], g_sbw[4*DM];
__device__ float  g_ao[(size_t)MTOT*DM];
__device__ __nv_bfloat16 g_Qh[(size_t)BB*HH*SS*DKK], g_Ql[(size_t)BB*HH*SS*DKK];
__device__ __nv_bfloat16 g_Kh[(size_t)BB*HH*SS*DKK], g_Kl[(size_t)BB*HH*SS*DKK];
__device__ __nv_bfloat16 g_Vh[(size_t)BB*HH*SS*DKK], g_Vl[(size_t)BB*HH*SS*DKK];
__device__ float g_rope[SS*64];   // [s][0..31]=cos, [s][32..63]=sin

#define ASCALE 0.1803368801111244f   // 1/sqrt(64)*log2(e)

// ---------------- PTX helpers (baseline ISA only) ----------------
__device__ __forceinline__ uint32_t smem_to_u32(const void* p) {
    uint32_t a;
    asm("{ .reg .u64 t; cvta.to.shared.u64 t, %1; cvt.u32.u64 %0, t; }"
        : "=r"(a) : "l"(p));
    return a;
}
__device__ __forceinline__ void cp16(uint32_t dst, const void* src) {
    asm volatile("cp.async.cg.shared.global [%0], [%1], 16;"
                 :: "r"(dst), "l"(src) : "memory");
}
#define CP_COMMIT() asm volatile("cp.async.commit_group;" ::: "memory")
#define CP_WAIT1()  asm volatile("cp.async.wait_group 1;"  ::: "memory")
#define CP_WAIT0()  asm volatile("cp.async.wait_group 0;"  ::: "memory")

__device__ __forceinline__ void ldsm4(uint32_t* r, uint32_t addr) {
    asm volatile("ldmatrix.sync.aligned.m8n8.x4.shared.b16 {%0,%1,%2,%3}, [%4];"
                 : "=r"(r[0]), "=r"(r[1]), "=r"(r[2]), "=r"(r[3]) : "r"(addr));
}
__device__ __forceinline__ void ldsm4t(uint32_t* r, uint32_t addr) {
    asm volatile("ldmatrix.sync.aligned.m8n8.x4.trans.shared.b16 {%0,%1,%2,%3}, [%4];"
                 : "=r"(r[0]), "=r"(r[1]), "=r"(r[2]), "=r"(r[3]) : "r"(addr));
}
__device__ __forceinline__ void mma16816(float* d, const uint32_t* a,
                                         uint32_t b0, uint32_t b1) {
    asm volatile("mma.sync.aligned.m16n8k16.row.col.f32.bf16.bf16.f32 "
                 "{%0,%1,%2,%3}, {%4,%5,%6,%7}, {%8,%9}, {%0,%1,%2,%3};"
                 : "+f"(d[0]), "+f"(d[1]), "+f"(d[2]), "+f"(d[3])
                 : "r"(a[0]), "r"(a[1]), "r"(a[2]), "r"(a[3]), "r"(b0), "r"(b1));
}
__device__ __forceinline__ void imma16832(int* d, const uint32_t* a,
                                          uint32_t b0, uint32_t b1) {
    asm volatile("mma.sync.aligned.m16n8k32.row.col.s32.s8.s8.s32 "
                 "{%0,%1,%2,%3}, {%4,%5,%6,%7}, {%8,%9}, {%0,%1,%2,%3};"
                 : "+r"(d[0]), "+r"(d[1]), "+r"(d[2]), "+r"(d[3])
                 : "r"(a[0]), "r"(a[1]), "r"(a[2]), "r"(a[3]), "r"(b0), "r"(b1));
}
__device__ __forceinline__ float ex2(float x) {
    float y;
    asm("ex2.approx.f32 %0, %1;" : "=f"(y) : "f"(x));
    return y;
}
__device__ __forceinline__ uint32_t packbf(float lo, float hi) {
    uint32_t r;
    asm("cvt.rn.bf16x2.f32 %0, %1, %2;" : "=r"(r) : "f"(hi), "f"(lo));
    return r;
}
__device__ __forceinline__ void split2(float d0, float d1, uint32_t& uh, uint32_t& ul) {
    uh = packbf(d0, d1);
    float h0 = __uint_as_float(uh << 16);
    float h1 = __uint_as_float(uh & 0xffff0000u);
    ul = packbf(d0 - h0, d1 - h1);
}

// ---------------------------------------------------------------------------
// Row quantization: fp32 row (1024) -> 2 int8 digit rows + scale.
// A ~= s*(A1 + A2/128), |A1|<=127, |A2|<=64, |residual| <= s/256.
// ---------------------------------------------------------------------------
__device__ __forceinline__ void quant_row_body(const float* __restrict__ srow,
                                               int8_t* __restrict__ s1,
                                               int8_t* __restrict__ s2,
                                               float* __restrict__ scale_out)
{
    __shared__ float red[8];
    const int t = threadIdx.x;
    float4 v = ((const float4*)srow)[t];
    float mx = fmaxf(fmaxf(fabsf(v.x), fabsf(v.y)), fmaxf(fabsf(v.z), fabsf(v.w)));
#pragma unroll
    for (int o = 16; o; o >>= 1) mx = fmaxf(mx, __shfl_xor_sync(0xffffffffu, mx, o));
    if ((t & 31) == 0) red[t >> 5] = mx;
    __syncthreads();
    if (t < 8) {
        float m2 = red[t];
#pragma unroll
        for (int o = 4; o; o >>= 1) m2 = fmaxf(m2, __shfl_xor_sync(0x000000ffu, m2, o));
        if (t == 0) red[0] = m2;
    }
    __syncthreads();
    const float m = fmaxf(red[0], 1e-20f);
    const float inv = 127.0f / m;
    if (t == 0) *scale_out = m * (1.0f / 127.0f);
    float q1x = rintf(v.x * inv), q1y = rintf(v.y * inv);
    float q1z = rintf(v.z * inv), q1w = rintf(v.w * inv);
    float q2x = rintf((v.x * inv - q1x) * 128.0f);
    float q2y = rintf((v.y * inv - q1y) * 128.0f);
    float q2z = rintf((v.z * inv - q1z) * 128.0f);
    float q2w = rintf((v.w * inv - q1w) * 128.0f);
    ((char4*)s1)[t] = make_char4((int)q1x, (int)q1y, (int)q1z, (int)q1w);
    ((char4*)s2)[t] = make_char4((int)q2x, (int)q2y, (int)q2z, (int)q2w);
}

__global__ void quant_x(const float* __restrict__ src, int8_t* s1, int8_t* s2, float* sc)
{
    size_t r = blockIdx.x;
    quant_row_body(src + r * DM, s1 + r * DM, s2 + r * DM, sc + r);
}

__global__ void quant_w4(const float* __restrict__ w0, const float* __restrict__ w1,
                         const float* __restrict__ w2, const float* __restrict__ w3,
                         int8_t* s1, int8_t* s2, float* sc)
{
    const int wsel = blockIdx.y;
    const float* src = (wsel == 0) ? w0 : (wsel == 1) ? w1 : (wsel == 2) ? w2 : w3;
    size_t r = blockIdx.x;
    size_t off = (size_t)wsel * DM * DM;
    quant_row_body(src + r * DM, s1 + off + r * DM, s2 + off + r * DM,
                   sc + wsel * DM + r);
}

__global__ void rope_init_kernel(const int* __restrict__ tokpos, float* __restrict__ rope)
{
    int idx = blockIdx.x * blockDim.x + threadIdx.x;
    int s = idx >> 5, p = idx & 31;
    float fr = (float)exp2(-(double)p * (13.287712379549449 / 32.0));
    float ang = (float)tokpos[s] * fr;
    float sn, cs;
    sincosf(ang, &sn, &cs);
    rope[s * 64 + p] = cs;
    rope[s * 64 + 32 + p] = sn;
}

// ---------------------------------------------------------------------------
// int8 2-digit GEMM: C[m,e] = sa[m]*sb[e]*(D1 + D2/128),
//   D1 = A1*B1, D2 = A1*B2 + A2*B1  (int32, exact).
// CTA tile 128x64, warp tile 32x32 (4m x 2n warps), K-stage 64, 2-stage pipe.
// wsel 0: rope*ASCALE -> Q hi/lo; 1: rope -> K; 2: -> V; 3: fp32 -> out.
// ---------------------------------------------------------------------------
#define IP     80
#define IA_T   (128*IP)            // 10240
#define IB_T   (64*IP)             // 5120
#define ISTG   (2*IA_T + 2*IB_T)   // 30720
#define IGSMEM (2*ISTG)            // 61440

__device__ __forceinline__ void issue_i8(uint32_t sdst,
    const int8_t* __restrict__ A1, const int8_t* __restrict__ A2,
    const int8_t* __restrict__ B1, const int8_t* __restrict__ B2,
    int m0, int n0, int kc, int tid)
{
    const int colb = kc * 64;
#pragma unroll
    for (int it = 0; it < 2; it++) {
        int idx = tid + it * 256;          // 0..511
        int row = idx >> 2;
        int ch  = (idx & 3) * 16;
        uint32_t soff = row * IP + ch;
        cp16(sdst + soff,        A1 + (size_t)(m0 + row) * DM + colb + ch);
        cp16(sdst + IA_T + soff, A2 + (size_t)(m0 + row) * DM + colb + ch);
    }
    {
        int row = tid >> 2;                // 0..63
        int ch  = (tid & 3) * 16;
        uint32_t soff = row * IP + ch;
        cp16(sdst + 2 * IA_T + soff,        B1 + (size_t)(n0 + row) * DM + colb + ch);
        cp16(sdst + 2 * IA_T + IB_T + soff, B2 + (size_t)(n0 + row) * DM + colb + ch);
    }
}

__global__ __launch_bounds__(256, 2)
void gemm_i8(const int8_t* __restrict__ A1, const int8_t* __restrict__ A2,
             const float* __restrict__ sa,
             const int8_t* __restrict__ W1, const int8_t* __restrict__ W2,
             const float* __restrict__ sbAll,
             float* __restrict__ out,
             __nv_bfloat16* __restrict__ qh, __nv_bfloat16* __restrict__ ql,
             __nv_bfloat16* __restrict__ kh, __nv_bfloat16* __restrict__ kl,
             __nv_bfloat16* __restrict__ vvh, __nv_bfloat16* __restrict__ vvl,
             const float* __restrict__ rope, int wo)
{
    extern __shared__ char smc[];
    const uint32_t sbase = smem_to_u32(smc);

    const int tid  = threadIdx.x;
    const int wid  = tid >> 5;
    const int lane = tid & 31;
    const int m0 = blockIdx.x * 128;
    const int by = blockIdx.y;
    const int wsel = wo ? 3 : (by >> 4);
    const int n0 = (by & 15) * 64;
    const int8_t* B1 = W1 + (size_t)wsel * DM * DM;
    const int8_t* B2 = W2 + (size_t)wsel * DM * DM;
    const float*  sb = sbAll + wsel * DM;

    const int wm = (wid & 3) * 32;
    const int wn = (wid >> 2) * 32;

    int d1[2][4][4], d2[2][4][4];
#pragma unroll
    for (int i = 0; i < 2; i++)
#pragma unroll
        for (int j = 0; j < 4; j++)
#pragma unroll
            for (int q = 0; q < 4; q++) { d1[i][j][q] = 0; d2[i][j][q] = 0; }

    const uint32_t lrow = (lane & 7) + ((lane >> 3) & 1) * 8;
    const uint32_t kb16 = ((lane >> 4) & 1) * 16;

    issue_i8(sbase, A1, A2, B1, B2, m0, n0, 0, tid);
    CP_COMMIT();

    const int NKC = DM / 64;   // 16
    for (int kc = 0; kc < NKC; kc++) {
        if (kc + 1 < NKC) {
            issue_i8(sbase + ((kc + 1) & 1) * ISTG, A1, A2, B1, B2, m0, n0, kc + 1, tid);
            CP_COMMIT();
            CP_WAIT1();
        } else {
            CP_WAIT0();
        }
        __syncthreads();

        const uint32_t sbs = sbase + (kc & 1) * ISTG;
#pragma unroll
        for (int ks = 0; ks < 2; ks++) {
            uint32_t a1f[2][4], a2f[2][4];
            const uint32_t abase = sbs + (wm + lrow) * IP + ks * 32 + kb16;
            ldsm4(a1f[0], abase);
            ldsm4(a1f[1], abase + 16 * IP);
            ldsm4(a2f[0], abase + IA_T);
            ldsm4(a2f[1], abase + IA_T + 16 * IP);
#pragma unroll
            for (int ntp = 0; ntp < 2; ntp++) {
                uint32_t b1f[4], b2f[4];
                const uint32_t bb = sbs + 2 * IA_T + (wn + ntp * 16 + lrow) * IP
                                  + ks * 32 + kb16;
                ldsm4(b1f, bb);
                ldsm4(b2f, bb + IB_T);
#pragma unroll
                for (int sel = 0; sel < 2; sel++) {
                    const int nj = ntp * 2 + sel;
                    const uint32_t p0 = b1f[sel], p1 = b1f[sel + 2];
                    const uint32_t q0 = b2f[sel], q1 = b2f[sel + 2];
#pragma unroll
                    for (int mi = 0; mi < 2; mi++) {
                        imma16832(d1[mi][nj], a1f[mi], p0, p1);
                        imma16832(d2[mi][nj], a1f[mi], q0, q1);
                        imma16832(d2[mi][nj], a2f[mi], p0, p1);
                    }
                }
            }
        }
        __syncthreads();
    }

    // ---- epilogue ----
    __nv_bfloat16 *oh = qh, *ol = ql;
    if (wsel == 1) { oh = kh; ol = kl; }
    else if (wsel == 2) { oh = vvh; ol = vvl; }

    const int g = lane >> 2;
    const int t2 = (lane & 3) * 2;
#pragma unroll
    for (int mi = 0; mi < 2; mi++) {
#pragma unroll
        for (int half = 0; half < 2; half++) {
            const int r = m0 + wm + mi * 16 + half * 8 + g;
            const float sar = sa[r];
            const int b = r >> 11;
            const int s = r & 2047;
#pragma unroll
            for (int nj = 0; nj < 4; nj++) {
                const int e = n0 + wn + nj * 8 + t2;
                const float2 sbe = *(const float2*)&sb[e];
                float d0 = (__int2float_rn(d1[mi][nj][half * 2 + 0])
                          + __int2float_rn(d2[mi][nj][half * 2 + 0]) * 0.0078125f)
                          * (sar * sbe.x);
                float d1v = (__int2float_rn(d1[mi][nj][half * 2 + 1])
                          + __int2float_rn(d2[mi][nj][half * 2 + 1]) * 0.0078125f)
                          * (sar * sbe.y);
                if (wsel == 3) {
                    *(float2*)&out[(size_t)r * DM + e] = make_float2(d0, d1v);
                } else {
                    const int h  = e >> 6;
                    const int dk = e & 63;
                    if (wsel <= 1) {
                        const int p = dk >> 1;
                        float cs = __ldg(&rope[s * 64 + p]);
                        float sn = __ldg(&rope[s * 64 + 32 + p]);
                        float r0 = d0 * cs - d1v * sn;
                        float r1 = d0 * sn + d1v * cs;
                        d0 = r0; d1v = r1;
                        if (wsel == 0) { d0 *= ASCALE; d1v *= ASCALE; }
                    }
                    size_t idx = ((size_t)(b * HH + h) * SS + s) * DKK + dk;
                    uint32_t uh, ul;
                    split2(d0, d1v, uh, ul);
                    *(uint32_t*)&oh[idx] = uh;
                    *(uint32_t*)&ol[idx] = ul;
                }
            }
        }
    }
}

// ---------------------------------------------------------------------------
// Tensor-core flash attention (bf16x3, causal) — validated; epilogue -> fp32 AO.
// ---------------------------------------------------------------------------
#define AP      144
#define QT_B    (128*AP)      // 18432
#define KT_B    (64*AP)       // 9216
#define ASTG_B  (4*KT_B)      // 36864
#define ASMEM   (2*QT_B + 2*ASTG_B)   // 110592

__device__ __forceinline__ void issue_kv(uint32_t dst,
    const __nv_bfloat16* __restrict__ Kh, const __nv_bfloat16* __restrict__ Kl,
    const __nv_bfloat16* __restrict__ Vh, const __nv_bfloat16* __restrict__ Vl,
    size_t base, int kb, int tid)
{
#pragma unroll
    for (int it = 0; it < 8; it++) {
        int f   = tid + it * 256;
        int ten = f >> 9;
        int row = (f >> 3) & 63;
        int ch  = f & 7;
        const __nv_bfloat16* sp = (ten == 0) ? Kh : (ten == 1) ? Kl
                                 : (ten == 2) ? Vh : Vl;
        sp += base + (size_t)(kb * 64 + row) * DKK + ch * 8;
        cp16(dst + ten * KT_B + row * AP + ch * 16, sp);
    }
}

__global__ __launch_bounds__(256, 2)
void attn_mma(const __nv_bfloat16* __restrict__ Qh, const __nv_bfloat16* __restrict__ Ql,
              const __nv_bfloat16* __restrict__ Kh, const __nv_bfloat16* __restrict__ Kl,
              const __nv_bfloat16* __restrict__ Vh, const __nv_bfloat16* __restrict__ Vl,
              float* __restrict__ AO)
{
    extern __shared__ char smc[];
    const uint32_t sb = smem_to_u32(smc);
    const uint32_t sQ  = sb;
    const uint32_t sKV = sb + 2 * QT_B;

    const int tid  = threadIdx.x;
    const int wid  = tid >> 5;
    const int lane = tid & 31;
    const int g = lane >> 2;
    const int t = lane & 3;

    const int qb = 15 - (blockIdx.x >> 6);
    const int bh = blockIdx.x & 63;
    const size_t base = (size_t)bh * SS * DKK;
    const int nkb = 2 * qb + 2;

    const float NINF = __int_as_float(0xff800000);

#pragma unroll
    for (int it = 0; it < 8; it++) {
        int f   = tid + it * 256;
        int ten = f >> 10;
        int row = (f >> 3) & 127;
        int ch  = f & 7;
        const __nv_bfloat16* sp = (ten ? Ql : Qh)
            + base + (size_t)(qb * 128 + row) * DKK + ch * 8;
        cp16(sQ + ten * QT_B + row * AP + ch * 16, sp);
    }
    issue_kv(sKV, Kh, Kl, Vh, Vl, base, 0, tid);
    CP_COMMIT();
    issue_kv(sKV + ASTG_B, Kh, Kl, Vh, Vl, base, 1, tid);
    CP_COMMIT();

    CP_WAIT1();
    __syncthreads();

    const uint32_t lrow = (lane & 7) + ((lane >> 3) & 1) * 8;
    const uint32_t kb16 = ((lane >> 4) & 1) * 16;
    uint32_t qfh[4][4], qfl[4][4];
#pragma unroll
    for (int ks = 0; ks < 4; ks++) {
        uint32_t a = sQ + (wid * 16 + lrow) * AP + ks * 32 + kb16;
        ldsm4(qfh[ks], a);
        ldsm4(qfl[ks], a + QT_B);
    }

    float oacc[8][4];
#pragma unroll
    for (int nj = 0; nj < 8; nj++)
#pragma unroll
        for (int q = 0; q < 4; q++) oacc[nj][q] = 0.f;
    float m0 = NINF, m1 = NINF, l0 = 0.f, l1 = 0.f;

    const int r0 = qb * 128 + wid * 16 + g;
    const int r1 = r0 + 8;

    const uint32_t vrow = (lane & 7) + ((lane >> 4) & 1) * 8;
    const uint32_t vb16 = ((lane >> 3) & 1) * 16;

    for (int kb = 0; kb < nkb; kb++) {
        if (kb + 1 < nkb) CP_WAIT1(); else CP_WAIT0();
        __syncthreads();

        const uint32_t sK = sKV + (kb & 1) * ASTG_B;
        const uint32_t sV = sK + 2 * KT_B;

        float sf[8][4];
#pragma unroll
        for (int nj = 0; nj < 8; nj++)
#pragma unroll
            for (int q = 0; q < 4; q++) sf[nj][q] = 0.f;

#pragma unroll
        for (int ks = 0; ks < 4; ks++) {
#pragma unroll
            for (int ntp = 0; ntp < 2; ntp++) {
                uint32_t kfh[2][4], kfl[2][4];
#pragma unroll
                for (int nt2 = 0; nt2 < 2; nt2++) {
                    uint32_t ba = sK + ((ntp * 2 + nt2) * 16 + lrow) * AP + ks * 32 + kb16;
                    ldsm4(kfh[nt2], ba);
                    ldsm4(kfl[nt2], ba + KT_B);
                }
#pragma unroll
                for (int term = 0; term < 3; term++) {
                    const uint32_t* a = (term == 2) ? qfl[ks] : qfh[ks];
#pragma unroll
                    for (int nt2 = 0; nt2 < 2; nt2++) {
#pragma unroll
                        for (int sel = 0; sel < 2; sel++) {
                            const int nj = (ntp * 2 + nt2) * 2 + sel;
                            const uint32_t b0 = (term == 1) ? kfl[nt2][sel]     : kfh[nt2][sel];
                            const uint32_t b1 = (term == 1) ? kfl[nt2][sel + 2] : kfh[nt2][sel + 2];
                            mma16816(sf[nj], a, b0, b1);
                        }
                    }
                }
            }
        }

        if (kb >= 2 * qb) {
#pragma unroll
            for (int nj = 0; nj < 8; nj++) {
                int c0 = kb * 64 + nj * 8 + 2 * t;
                if (c0 > r0)     sf[nj][0] = NINF;
                if (c0 + 1 > r0) sf[nj][1] = NINF;
                if (c0 > r1)     sf[nj][2] = NINF;
                if (c0 + 1 > r1) sf[nj][3] = NINF;
            }
        }

        float mx0 = sf[0][0], mx1 = sf[0][2];
#pragma unroll
        for (int nj = 0; nj < 8; nj++) {
            mx0 = fmaxf(mx0, fmaxf(sf[nj][0], sf[nj][1]));
            mx1 = fmaxf(mx1, fmaxf(sf[nj][2], sf[nj][3]));
        }
        mx0 = fmaxf(mx0, __shfl_xor_sync(0xffffffffu, mx0, 1));
        mx0 = fmaxf(mx0, __shfl_xor_sync(0xffffffffu, mx0, 2));
        mx1 = fmaxf(mx1, __shfl_xor_sync(0xffffffffu, mx1, 1));
        mx1 = fmaxf(mx1, __shfl_xor_sync(0xffffffffu, mx1, 2));
        float mn0 = fmaxf(m0, mx0), mn1 = fmaxf(m1, mx1);
        float al0 = ex2(m0 - mn0), al1 = ex2(m1 - mn1);
        m0 = mn0; m1 = mn1;

        float s0 = 0.f, s1 = 0.f;
#pragma unroll
        for (int nj = 0; nj < 8; nj++) {
            sf[nj][0] = ex2(sf[nj][0] - m0);
            sf[nj][1] = ex2(sf[nj][1] - m0);
            sf[nj][2] = ex2(sf[nj][2] - m1);
            sf[nj][3] = ex2(sf[nj][3] - m1);
            s0 += sf[nj][0] + sf[nj][1];
            s1 += sf[nj][2] + sf[nj][3];
        }
        s0 += __shfl_xor_sync(0xffffffffu, s0, 1);
        s0 += __shfl_xor_sync(0xffffffffu, s0, 2);
        s1 += __shfl_xor_sync(0xffffffffu, s1, 1);
        s1 += __shfl_xor_sync(0xffffffffu, s1, 2);
        l0 = l0 * al0 + s0;
        l1 = l1 * al1 + s1;

#pragma unroll
        for (int nj = 0; nj < 8; nj++) {
            oacc[nj][0] *= al0; oacc[nj][1] *= al0;
            oacc[nj][2] *= al1; oacc[nj][3] *= al1;
        }

#pragma unroll
        for (int ks = 0; ks < 4; ks++) {
            uint32_t pah[4], pal[4];
            split2(sf[2 * ks][0],     sf[2 * ks][1],     pah[0], pal[0]);
            split2(sf[2 * ks][2],     sf[2 * ks][3],     pah[1], pal[1]);
            split2(sf[2 * ks + 1][0], sf[2 * ks + 1][1], pah[2], pal[2]);
            split2(sf[2 * ks + 1][2], sf[2 * ks + 1][3], pah[3], pal[3]);
#pragma unroll
            for (int ntp = 0; ntp < 2; ntp++) {
                uint32_t vfh[2][4], vfl[2][4];
#pragma unroll
                for (int nt2 = 0; nt2 < 2; nt2++) {
                    uint32_t va = sV + (ks * 16 + vrow) * AP + (ntp * 2 + nt2) * 32 + vb16;
                    ldsm4t(vfh[nt2], va);
                    ldsm4t(vfl[nt2], va + KT_B);
                }
#pragma unroll
                for (int term = 0; term < 3; term++) {
                    const uint32_t* a = (term == 2) ? pal : pah;
#pragma unroll
                    for (int nt2 = 0; nt2 < 2; nt2++) {
#pragma unroll
                        for (int sel = 0; sel < 2; sel++) {
                            const int nj = (ntp * 2 + nt2) * 2 + sel;
                            const uint32_t b0 = (term == 1) ? vfl[nt2][sel]     : vfh[nt2][sel];
                            const uint32_t b1 = (term == 1) ? vfl[nt2][sel + 2] : vfh[nt2][sel + 2];
                            mma16816(oacc[nj], a, b0, b1);
                        }
                    }
                }
            }
        }
        __syncthreads();

        if (kb + 2 < nkb) {
            issue_kv(sKV + (kb & 1) * ASTG_B, Kh, Kl, Vh, Vl, base, kb + 2, tid);
            CP_COMMIT();
        }
    }

    // ---- epilogue: fp32 AO at [b*S+s][h*64+dk] ----
    const float inv0 = 1.0f / l0;
    const float inv1 = 1.0f / l1;
    const int b = bh >> 4, h = bh & 15;
    const size_t row0 = (size_t)(b * SS + r0) * DM;
    const size_t row1 = (size_t)(b * SS + r1) * DM;
#pragma unroll
    for (int nj = 0; nj < 8; nj++) {
        const int e = h * 64 + nj * 8 + 2 * t;
        *(float2*)&AO[row0 + e] = make_float2(oacc[nj][0] * inv0, oacc[nj][1] * inv0);
        *(float2*)&AO[row1 + e] = make_float2(oacc[nj][2] * inv1, oacc[nj][3] * inv1);
    }
}

// ---------------------------------------------------------------------------
extern "C" void kernel_launch(void* const* d_in, const int* in_sizes, int n_in,
                              void* d_out, int out_size)
{
    const float* x  = (const float*)d_in[0];
    const float* Wq = (const float*)d_in[1];
    const float* Wk = (const float*)d_in[2];
    const float* Wv = (const float*)d_in[3];
    const float* Wo = (const float*)d_in[4];
    const int*   tp = (const int*)  d_in[5];
    float* out = (float*)d_out;

    float *gRope, *gAO, *gSax, *gSaao, *gSbw;
    int8_t *x1, *x2, *w1, *w2, *a1, *a2;
    __nv_bfloat16 *qh, *ql, *kh, *kl, *vh, *vl;
    cudaGetSymbolAddress((void**)&gRope, g_rope);
    cudaGetSymbolAddress((void**)&gAO,   g_ao);
    cudaGetSymbolAddress((void**)&gSax,  g_sax);
    cudaGetSymbolAddress((void**)&gSaao, g_saao);
    cudaGetSymbolAddress((void**)&gSbw,  g_sbw);
    cudaGetSymbolAddress((void**)&x1, g_x1);
    cudaGetSymbolAddress((void**)&x2, g_x2);
    cudaGetSymbolAddress((void**)&w1, g_w1);
    cudaGetSymbolAddress((void**)&w2, g_w2);
    cudaGetSymbolAddress((void**)&a1, g_a1);
    cudaGetSymbolAddress((void**)&a2, g_a2);
    cudaGetSymbolAddress((void**)&qh, g_Qh);
    cudaGetSymbolAddress((void**)&ql, g_Ql);
    cudaGetSymbolAddress((void**)&kh, g_Kh);
    cudaGetSymbolAddress((void**)&kl, g_Kl);
    cudaGetSymbolAddress((void**)&vh, g_Vh);
    cudaGetSymbolAddress((void**)&vl, g_Vl);

    cudaFuncSetAttribute(gemm_i8, cudaFuncAttributeMaxDynamicSharedMemorySize, IGSMEM);
    cudaFuncSetAttribute(attn_mma, cudaFuncAttributeMaxDynamicSharedMemorySize, ASMEM);

    quant_x<<<MTOT, 256>>>(x, x1, x2, gSax);
    dim3 wgrid(DM, 4);
    quant_w4<<<wgrid, 256>>>(Wq, Wk, Wv, Wo, w1, w2, gSbw);
    rope_init_kernel<<<SS * 32 / 256, 256>>>(tp, gRope);

    // fused QKV projections: grid (64, 48), wsel = by>>4, n0 = (by&15)*64
    dim3 qkvgrid(MTOT / 128, 48);
    gemm_i8<<<qkvgrid, 256, IGSMEM>>>(x1, x2, gSax, w1, w2, gSbw, nullptr,
                                      qh, ql, kh, kl, vh, vl, gRope, 0);

    attn_mma<<<1024, 256, ASMEM>>>(qh, ql, kh, kl, vh, vl, gAO);

    quant_x<<<MTOT, 256>>>(gAO, a1, a2, gSaao);

    // Wo projection: grid (64, 16), wsel = 3
    dim3 wogrid(MTOT / 128, 16);
    gemm_i8<<<wogrid, 256, IGSMEM>>>(a1, a2, gSaao, w1, w2, gSbw, out,
                                     qh, ql, kh, kl, vh, vl, gRope, 1);
}